// round 12
// baseline (speedup 1.0000x reference)
#include <cuda_runtime.h>
#include <cstdint>

// Output layout (floats), tuple order (c_all, y_all, GBT_A, GBT_B):
//   c_all : [1024,256]      offset 0        size 262144
//   y_all : [1024]          offset 262144   size 1024
//   GBT_A : [1024,256,256]  offset 263168   size 67108864
//   GBT_B : [1024,256]      offset 67372032 size 262144
#define OC 0
#define OY 262144
#define OA 263168
#define OB 67372032

#define QE 512
// dynamic smem layout (scan block only):
//   tab : float2[1024]      @ 0       (8192 B)
//   Q   : float2[7][QE]     @ 8192    (28672 B)
//   stg : float[8][64*32]   @ 36864   (65536 B)
//   pc  : int[8]            @ 102400  (producer progress, timesteps)
//   cc  : int[8]            @ 102432  (consumer progress, iters)
#define SMEMB (102400 + 64)

static __device__ __forceinline__ float frcp(float x) {
    float y; asm("rcp.approx.ftz.f32 %0,%1;" : "=f"(y) : "f"(x)); return y;
}

__global__ __launch_bounds__(256) void hippo_fused(
    const float* __restrict__ f,
    const float* __restrict__ init_state,
    const float* __restrict__ Bv,
    float* __restrict__ out)
{
    extern __shared__ char dsm[];
    const int bid = blockIdx.x;
    const int tid = threadIdx.x;

    if (bid == 0) {
        // ======= scan: c_all + y_all; 8 compute warps, warp-pipelined =======
        // c_k = P1_k^{-1}(2 c_{k-1} + s_k f_k B) - c_{k-1}; O(N) solve:
        //   x_i = (u_i - h r_i S_i)/d_i ;  S_{i+1} = S_i + r_i x_i
        // Warp w owns elements [32w,32w+32); lane j at iter t does k=t-j.
        // Cross-warp (S,y) via smem queues + release/acquire counters (no BAR).
        float2* tab = (float2*)dsm;
        float2* Q   = (float2*)(dsm + 8192);
        float*  stg = (float*)(dsm + 36864);

        for (int kq = tid; kq < 1024; kq += 256) {
            float s = frcp((float)(kq + 1));
            tab[kq] = make_float2(s * f[kq], 0.5f * s);
        }
        if (tid < 16) ((int*)(dsm + 102400))[tid] = 0;
        __syncthreads();                                 // one-time only

        const int w = tid >> 5, lane = tid & 31;
        const int el = (w << 5) + lane;
        const float r   = __ldg(Bv + el);
        const float ipf = (float)(el + 1);
        float c = init_state[el];

        float2* Qin  = Q + (w - 1) * QE;                 // used only when w>0
        float2* Qout = Q + w * QE;                       // used only when w<7
        float*  stg_w = stg + (w << 11);
        const uint32_t pcin_a  = (uint32_t)__cvta_generic_to_shared((int*)(dsm + 102400) + (w - 1));
        const uint32_t pcout_a = (uint32_t)__cvta_generic_to_shared((int*)(dsm + 102400) + w);
        const uint32_t ccme_a  = (uint32_t)__cvta_generic_to_shared((int*)(dsm + 102432) + w);
        const uint32_t ccnx_a  = (uint32_t)__cvta_generic_to_shared((int*)(dsm + 102432) + w + 1);

        float Sin = 0.f, yin = 0.f;
        int avail = 0;

        for (int t = 0; t < 1056; t++) {
            const int  k     = t - lane;
            const bool valid = ((unsigned)k < 1024u);

            // lane 0 input: from predecessor warp's queue (timestep t)
            if (w > 0 && lane == 0 && t < 1024) {
                if (avail <= t) {
                    do {
                        asm volatile("ld.acquire.cta.shared.b32 %0,[%1];"
                                     : "=r"(avail) : "r"(pcin_a) : "memory");
                    } while (avail <= t);
                }
                float2 q = Qin[t & (QE - 1)];
                Sin = q.x; yin = q.y;
            }
            if (w == 0 && lane == 0) { Sin = 0.f; yin = 0.f; }

            float2 th = tab[valid ? k : 0];
            const float sf = th.x, h = th.y;
            float iv   = frcp(fmaf(h, ipf, 1.0f));
            float u    = fmaf(sf, r, c + c);
            float x    = fmaf(-h * r, Sin, u) * iv;
            float Sout = fmaf(r, x, Sin);
            float cn   = x - c;
            float yout = yin + cn;

            if (valid) {
                c = cn;
                stg_w[((k & 63) << 5) + lane] = cn;      // bank=lane, same-thread r/w
                if (lane == 31) {
                    if (w < 7) {
                        Qout[k & (QE - 1)] = make_float2(Sout, yout);
                        if ((k & 15) == 15) {
                            int P = k + 1;
                            asm volatile("st.release.cta.shared.b32 [%0],%1;"
                                         :: "r"(pcout_a), "r"(P) : "memory");
                        }
                    } else {
                        out[OY + k] = yout;              // element 255 completes y_k
                    }
                }
            }

            float nS = __shfl_up_sync(0xffffffffu, Sout, 1);
            float ny = __shfl_up_sync(0xffffffffu, yout, 1);
            if (lane > 0) { Sin = nS; yin = ny; }

            if ((t & 31) == 31) {
                // flush rows [t-63, t-32] of this warp's 32-col slice (coalesced)
                int row0 = t - 63;
                if (row0 >= 0) {
                    #pragma unroll 4
                    for (int rr = 0; rr < 32; rr++) {
                        int row = row0 + rr;
                        float v = stg_w[((row & 63) << 5) + lane];
                        out[OC + ((size_t)row << 8) + (w << 5) + lane] = v;
                    }
                }
                // consumer progress publish + producer backpressure
                if (w > 0 && lane == 0) {
                    asm volatile("st.relaxed.cta.shared.b32 [%0],%1;"
                                 :: "r"(ccme_a), "r"(t) : "memory");
                }
                if (w < 7) {
                    int need = t - 448;                  // queue slack guard
                    if (need > 0) {
                        int cp;
                        do {
                            asm volatile("ld.relaxed.cta.shared.b32 %0,[%1];"
                                         : "=r"(cp) : "r"(ccnx_a) : "memory");
                        } while (cp < need);
                    }
                }
            }
        }
    } else if (bid <= 256) {
        // ========== GBT_A sweep: 4 timesteps per block ==========
        __shared__ float t_sh[4][256];
        const int grp = tid >> 6;
        const int g   = tid & 63;
        const int k   = ((bid - 1) << 2) + grp;
        const float s = frcp((float)(k + 1));
        const float h = 0.5f * s;

        #pragma unroll
        for (int m = 0; m < 4; m++) {
            int i = g + (m << 6);
            float tv = 0.0f;
            if (i >= 1) {
                float ri  = __ldg(Bv + i);
                float rim = __ldg(Bv + i - 1);
                float di  = fmaf(h, (float)(i + 1), 1.0f);
                tv = ri * (1.0f - h * (float)(i - 1)) * frcp(rim * di);
            }
            t_sh[grp][i] = tv;
        }
        __syncthreads();

        const int j0 = g << 2;
        float invd[5];
        #pragma unroll
        for (int m = 0; m < 5; m++)
            invd[m] = frcp(fmaf(h, (float)(j0 + m + 1), 1.0f));

        float diag[4], start[4], val[4];
        #pragma unroll
        for (int m = 0; m < 4; m++) {
            int j = j0 + m;
            diag[m] = (1.0f - h * (float)(j + 1)) * invd[m];
            float rj  = __ldg(Bv + j);
            float rj1 = (j + 1 < 256) ? __ldg(Bv + j + 1) : 0.0f;
            start[m] = -2.0f * h * rj1 * rj * invd[m] * invd[m + 1];
            val[m] = 0.0f;
        }

        float4* outp = (float4*)(out + OA + ((size_t)k << 16) + j0);
        for (int i = 0; i < 256; i++) {
            float tv = t_sh[grp][i];
            float4 v;
            #pragma unroll
            for (int m = 0; m < 4; m++) {
                int j = j0 + m;
                val[m] = (i == j + 1) ? start[m] : val[m] * tv;
                float vv = (i < j) ? 0.0f : ((i == j) ? diag[m] : val[m]);
                ((float*)&v)[m] = vv;
            }
            outp[(size_t)i << 6] = v;
        }
    } else {
        // ========== GBT_B: thread per timestep, float4-batched stores =====
        __shared__ float rsh[256];
        rsh[tid] = __ldg(Bv + tid);
        __syncthreads();
        const int k = ((bid - 257) << 8) + tid;
        const float s = frcp((float)(k + 1));
        const float h = 0.5f * s;
        float S = 0.0f;
        float4* outB = (float4*)(out + OB + ((size_t)k << 8));
        const float4* r4p = (const float4*)rsh;
        #pragma unroll 4
        for (int i4 = 0; i4 < 64; i4++) {
            float4 r4 = r4p[i4];
            float4 v;
            #pragma unroll
            for (int m = 0; m < 4; m++) {
                int i = (i4 << 2) + m;
                float r    = (&r4.x)[m];
                float invd = frcp(fmaf(h, (float)(i + 1), 1.0f));
                float x    = r * fmaf(-h, S, 1.0f) * invd;
                (&v.x)[m]  = s * x;
                S = fmaf(r, x, S);
            }
            outB[i4] = v;
        }
    }
}

extern "C" void kernel_launch(void* const* d_in, const int* in_sizes, int n_in,
                              void* d_out, int out_size) {
    const float* f          = (const float*)d_in[0];
    const float* init_state = (const float*)d_in[1];
    const float* Bv         = (const float*)d_in[3];
    cudaFuncSetAttribute(hippo_fused, cudaFuncAttributeMaxDynamicSharedMemorySize,
                         SMEMB);
    hippo_fused<<<261, 256, SMEMB>>>(f, init_state, Bv, (float*)d_out);
}

// round 15
// speedup vs baseline: 5.2962x; 5.2962x over previous
#include <cuda_runtime.h>
#include <cstdint>

// Output layout (floats), tuple order (c_all, y_all, GBT_A, GBT_B):
//   c_all : [1024,256]      offset 0        size 262144
//   y_all : [1024]          offset 262144   size 1024
//   GBT_A : [1024,256,256]  offset 263168   size 67108864
//   GBT_B : [1024,256]      offset 67372032 size 262144
#define OC 0
#define OY 262144
#define OA 263168
#define OB 67372032

static __device__ __forceinline__ float frcp(float x) {
    float y; asm("rcp.approx.ftz.f32 %0,%1;" : "=f"(y) : "f"(x)); return y;
}

__global__ __launch_bounds__(256) void hippo_fused(
    const float* __restrict__ f,
    const float* __restrict__ init_state,
    const float* __restrict__ Bv,
    float* __restrict__ out)
{
    __shared__ float2 tab[1024];      // (s_k*f_k, h_k)
    __shared__ float4 Qs[16];         // w0->w1 handoff, 8-iter skew, 16 deep
    __shared__ float  t_sh[4][256];   // sweep ratio table
    __shared__ float  rsh[256];       // GBT_B r cache

    const int bid = blockIdx.x;
    const int tid = threadIdx.x;

    if (bid == 0) {
        // ===== scan: c_all + y_all. 2 compute warps, bar every 8 iters =====
        // c_k = P1_k^{-1}(2 c_{k-1} + s_k f_k B) - c_{k-1}; O(N) solve:
        //   x_i = (u_i - h r_i S_i)/d_i ;  S_{i+1} = S_i + r_i x_i
        // Lane gl owns elems [4gl,4gl+4); 2 timesteps/iter; pair kd per lane:
        //   w0: kd = T - lane        w1: kd = T - 39 - lane  (32 skew + 8 buffer)
        for (int kq = tid; kq < 1024; kq += 256) {
            float s = frcp((float)(kq + 1));
            tab[kq] = make_float2(s * f[kq], 0.5f * s);
        }
        __syncthreads();                              // all 8 warps

        const int w = tid >> 5, lane = tid & 31;
        if (w >= 2) return;                           // bars below involve w0,w1 only

        const int gl   = (w << 5) + lane;             // 0..63
        const int offs = w ? (39 + lane) : lane;
        float r4[4], ipf[4], c4[4];
        {
            float4 rv = *(const float4*)(Bv + 4 * gl);
            float4 cv = *(const float4*)(init_state + 4 * gl);
            #pragma unroll
            for (int m = 0; m < 4; m++) {
                r4[m]  = (&rv.x)[m];
                ipf[m] = (float)(4 * gl + m + 1);
                c4[m]  = (&cv.x)[m];
            }
        }
        float Sin0 = 0.f, yin0 = 0.f, Sin1 = 0.f, yin1 = 0.f;
        const float4* tabq = (const float4*)tab;

        for (int T = 0; T < 584; T++) {               // 584 = 73*8
            const int  kd    = T - offs;
            const bool valid = ((unsigned)kd < 512u);

            if (w == 1 && lane == 0 && valid) {       // consume w0's iter T-8 output
                float4 q = Qs[(T - 8) & 15];
                Sin0 = q.x; yin0 = q.y; Sin1 = q.z; yin1 = q.w;
            }
            if (w == 0 && lane == 0) { Sin0 = 0.f; yin0 = 0.f; Sin1 = 0.f; yin1 = 0.f; }

            float4 tq = tabq[valid ? kd : 0];         // sf0,h0,sf1,h1
            const float sf0 = tq.x, h0 = tq.y, sf1 = tq.z, h1 = tq.w;

            float S0 = Sin0, y0 = yin0, S1 = Sin1, y1 = yin1;
            float cn0[4], cn1[4];
            #pragma unroll
            for (int m = 0; m < 4; m++) {
                float r = r4[m], c = c4[m];
                // timestep k0 = 2*kd
                float iv0 = frcp(fmaf(h0, ipf[m], 1.0f));
                float u0  = fmaf(sf0, r, c + c);
                float x0  = fmaf(-h0 * r, S0, u0) * iv0;
                S0        = fmaf(r, x0, S0);
                cn0[m]    = x0 - c;
                y0       += cn0[m];
                // timestep k0+1 (consumes cn0)
                float iv1 = frcp(fmaf(h1, ipf[m], 1.0f));
                float u1  = fmaf(sf1, r, cn0[m] + cn0[m]);
                float x1  = fmaf(-h1 * r, S1, u1) * iv1;
                S1        = fmaf(r, x1, S1);
                cn1[m]    = x1 - cn0[m];
                y1       += cn1[m];
            }

            if (valid) {
                #pragma unroll
                for (int m = 0; m < 4; m++) c4[m] = cn1[m];
                const int k0 = kd << 1;
                float* p = out + OC + ((size_t)k0 << 8) + 4 * gl;
                *(float4*)p         = make_float4(cn0[0], cn0[1], cn0[2], cn0[3]);
                *(float4*)(p + 256) = make_float4(cn1[0], cn1[1], cn1[2], cn1[3]);
                if (gl == 63) { out[OY + k0] = y0; out[OY + k0 + 1] = y1; }
            }
            if (w == 0 && lane == 31)
                Qs[T & 15] = make_float4(S0, y0, S1, y1);

            float nS0 = __shfl_up_sync(0xffffffffu, S0, 1);
            float ny0 = __shfl_up_sync(0xffffffffu, y0, 1);
            float nS1 = __shfl_up_sync(0xffffffffu, S1, 1);
            float ny1 = __shfl_up_sync(0xffffffffu, y1, 1);
            if (lane > 0) { Sin0 = nS0; yin0 = ny0; Sin1 = nS1; yin1 = ny1; }

            if ((T & 7) == 7) __syncthreads();        // w0+w1 only (others exited)
        }
    } else if (bid <= 256) {
        // ========== GBT_A sweep: 4 timesteps per block (proven form) ======
        const int grp = tid >> 6;
        const int g   = tid & 63;
        const int k   = ((bid - 1) << 2) + grp;
        const float s = frcp((float)(k + 1));
        const float h = 0.5f * s;

        #pragma unroll
        for (int m = 0; m < 4; m++) {
            int i = g + (m << 6);
            float tv = 0.0f;
            if (i >= 1) {
                float ri  = __ldg(Bv + i);
                float rim = __ldg(Bv + i - 1);
                float di  = fmaf(h, (float)(i + 1), 1.0f);
                tv = ri * (1.0f - h * (float)(i - 1)) * frcp(rim * di);
            }
            t_sh[grp][i] = tv;
        }
        __syncthreads();

        const int j0 = g << 2;
        float invd[5];
        #pragma unroll
        for (int m = 0; m < 5; m++)
            invd[m] = frcp(fmaf(h, (float)(j0 + m + 1), 1.0f));

        float diag[4], start[4], val[4];
        #pragma unroll
        for (int m = 0; m < 4; m++) {
            int j = j0 + m;
            diag[m] = (1.0f - h * (float)(j + 1)) * invd[m];
            float rj  = __ldg(Bv + j);
            float rj1 = (j + 1 < 256) ? __ldg(Bv + j + 1) : 0.0f;
            start[m] = -2.0f * h * rj1 * rj * invd[m] * invd[m + 1];
            val[m] = 0.0f;
        }

        float4* outp = (float4*)(out + OA + ((size_t)k << 16) + j0);
        for (int i = 0; i < 256; i++) {
            float tv = t_sh[grp][i];
            float4 v;
            #pragma unroll
            for (int m = 0; m < 4; m++) {
                int j = j0 + m;
                val[m] = (i == j + 1) ? start[m] : val[m] * tv;
                float vv = (i < j) ? 0.0f : ((i == j) ? diag[m] : val[m]);
                ((float*)&v)[m] = vv;
            }
            outp[(size_t)i << 6] = v;
        }
    } else {
        // ========== GBT_B: thread per timestep, float4-batched stores =====
        rsh[tid] = __ldg(Bv + tid);
        __syncthreads();
        const int k = ((bid - 257) << 8) + tid;
        const float s = frcp((float)(k + 1));
        const float h = 0.5f * s;
        float S = 0.0f;
        float4* outB = (float4*)(out + OB + ((size_t)k << 8));
        const float4* r4p = (const float4*)rsh;
        #pragma unroll 4
        for (int i4 = 0; i4 < 64; i4++) {
            float4 r4v = r4p[i4];
            float4 v;
            #pragma unroll
            for (int m = 0; m < 4; m++) {
                int i = (i4 << 2) + m;
                float r    = (&r4v.x)[m];
                float invd = frcp(fmaf(h, (float)(i + 1), 1.0f));
                float x    = r * fmaf(-h, S, 1.0f) * invd;
                (&v.x)[m]  = s * x;
                S = fmaf(r, x, S);
            }
            outB[i4] = v;
        }
    }
}

extern "C" void kernel_launch(void* const* d_in, const int* in_sizes, int n_in,
                              void* d_out, int out_size) {
    const float* f          = (const float*)d_in[0];
    const float* init_state = (const float*)d_in[1];
    const float* Bv         = (const float*)d_in[3];
    hippo_fused<<<261, 256>>>(f, init_state, Bv, (float*)d_out);
}